// round 10
// baseline (speedup 1.0000x reference)
#include <cuda_runtime.h>

// SparseBPNeuralNetwork — fused sparse BP decoder, round 10.
// Restructure vs round 9: HALF-CHECK threads (648 thr/block, 3 edges each),
// partner products exchanged via __shfl_xor -> ~half the regs & chain length,
// 2x warps/SM (launch_bounds(648,2) -> 40.5 warps/SM vs 20.25).

#define NV 648
#define NE 1944
#define BATCH 2048
#define NCHK 324
#define TOT ((size_t)BATCH * NV)
#define ROWS 2
#define THREADS NV          // 648 = 2 * NCHK

#define VCLAMP 17.0f            // keeps products < FLT_MAX
#define TVCLAMP 14.508657f      // = 2*atanh(0.999999)
#define LN2F 0.69314718056f

// ---- preprocessed graph/weight data ----
__device__ int    g_var_of[NE];     // edge -> variable
__device__ int    g_eov[NV * 3];    // var,layer -> edge (slot = layer = e/NV)
__device__ int    g_jp[NE];         // packed partners: j1 | (j2<<16)
__device__ float2 g_w[4][NE];       // per VN layer: (W[e][j1], W[e][j2])
__device__ float  g_w9[NV][3];      // output weights per var (3 edges)

// ---------------- preprocessing ----------------
#define SCAN4 (NV * NE / 4)

__global__ void prep1(const float4* __restrict__ M_out4) {
    int idx = blockIdx.x * blockDim.x + threadIdx.x;     // over NV*NE/4
    if (idx >= SCAN4) return;
    float4 val = M_out4[idx];
    if (val.x == 0.0f && val.y == 0.0f && val.z == 0.0f && val.w == 0.0f) return;
    int lin = idx * 4;
    int v = lin / NE;
    int e = lin - v * NE;
    float vv[4] = {val.x, val.y, val.z, val.w};
#pragma unroll
    for (int k = 0; k < 4; k++) {
        if (vv[k] != 0.0f) {
            int ek = e + k;
            g_var_of[ek] = v;
            g_eov[v * 3 + ek / NV] = ek;
        }
    }
}

__global__ void prep2(const float* __restrict__ W1, const float* __restrict__ W3,
                      const float* __restrict__ W5, const float* __restrict__ W7,
                      const float* __restrict__ W9) {
    int idx = blockIdx.x * blockDim.x + threadIdx.x;     // over 4*NE
    if (idx < 4 * NE) {
        int li = idx / NE;
        int e  = idx - li * NE;
        int v  = g_var_of[e];
        int l  = e / NV;
        int j1 = g_eov[v * 3 + ((l + 1) % 3)];
        int j2 = g_eov[v * 3 + ((l + 2) % 3)];
        const float* W = (li == 0) ? W1 : (li == 1) ? W3 : (li == 2) ? W5 : W7;
        g_w[li][e] = make_float2(W[(size_t)e * NE + j1], W[(size_t)e * NE + j2]);
        if (li == 0) g_jp[e] = j1 | (j2 << 16);
    }
    if (idx < NV) {
        int v = idx;
        g_w9[v][0] = W9[(size_t)v * NE + g_eov[v * 3 + 0]];
        g_w9[v][1] = W9[(size_t)v * NE + g_eov[v * 3 + 1]];
        g_w9[v][2] = W9[(size_t)v * NE + g_eov[v * 3 + 2]];
    }
}

// ---------------- fast math ----------------
__device__ __forceinline__ float sigmoidf(float s) {
    return __fdividef(1.0f, 1.0f + __expf(-s));
}

// Half-check CN update: this thread owns 3 of the 6 edges; the warp-adjacent
// partner thread (lane^1) owns the other 3. v[k] pre-tanh messages (rows x,y).
// tv[k] = 2*atanh(clamp(prod_{j!=k over all 6} tanh(v_j/2), +-0.999999)).
__device__ __forceinline__ void cn_half(unsigned mask, const float2 v[3], float2 tv[3]) {
    float2 n[3], d[3];
#pragma unroll
    for (int k = 0; k < 3; k++) {
        float ex = __expf(fminf(v[k].x, VCLAMP));
        float ey = __expf(fminf(v[k].y, VCLAMP));
        n[k] = make_float2(ex - 1.0f, ey - 1.0f);
        d[k] = make_float2(ex + 1.0f, ey + 1.0f);
    }
    // own pairwise products (leave-one-out over own 3)
    float2 n01 = make_float2(n[0].x * n[1].x, n[0].y * n[1].y);
    float2 n12 = make_float2(n[1].x * n[2].x, n[1].y * n[2].y);
    float2 n02 = make_float2(n[0].x * n[2].x, n[0].y * n[2].y);
    float2 d01 = make_float2(d[0].x * d[1].x, d[0].y * d[1].y);
    float2 d12 = make_float2(d[1].x * d[2].x, d[1].y * d[2].y);
    float2 d02 = make_float2(d[0].x * d[2].x, d[0].y * d[2].y);
    // own full 3-products -> exchange with partner half
    float pnx = n01.x * n[2].x, pny = n01.y * n[2].y;
    float pdx = d01.x * d[2].x, pdy = d01.y * d[2].y;
    float onx = __shfl_xor_sync(mask, pnx, 1);
    float ony = __shfl_xor_sync(mask, pny, 1);
    float odx = __shfl_xor_sync(mask, pdx, 1);
    float ody = __shfl_xor_sync(mask, pdy, 1);
    float2 qn[3] = {n12, n02, n01};
    float2 qd[3] = {d12, d02, d01};
#pragma unroll
    for (int k = 0; k < 3; k++) {
        float Px = qn[k].x * onx, Qx = qd[k].x * odx;    // products over the 5 others
        float Py = qn[k].y * ony, Qy = qd[k].y * ody;
        float nx = fmaxf(Qx + Px, 1e-33f), dx = fmaxf(Qx - Px, 1e-33f);
        float ny = fmaxf(Qy + Py, 1e-33f), dy = fmaxf(Qy - Py, 1e-33f);
        float tx = (__log2f(nx) - __log2f(dx)) * LN2F;
        float ty = (__log2f(ny) - __log2f(dy)) * LN2F;
        tv[k].x = fminf(fmaxf(tx, -TVCLAMP), TVCLAMP);   // == clamp m to +-0.999999
        tv[k].y = fminf(fmaxf(ty, -TVCLAMP), TVCLAMP);
    }
}

__global__ __launch_bounds__(THREADS, 2)
void bp_main(const float* __restrict__ x, float* __restrict__ out) {
    __shared__ float2 s_llr[NV];        // (row0, row1)
    __shared__ float2 s_t[2][NE];       // messages, row-interleaved

    const int b0  = blockIdx.x * ROWS;
    const int tid = threadIdx.x;        // 648 threads: check = tid>>1, half = tid&1
    const int c   = tid >> 1;
    const int h   = tid & 1;
    const int ebase = c * 6 + h * 3;    // this thread's 3 edges
    // 648 = 20 full warps + 8 lanes; pair (lane^1) is always inside the mask
    const unsigned mask = (tid >= 640) ? 0xffu : 0xffffffffu;

    // coalesced llr load; thread tid also owns output var v = tid
    float2 llrv;
    llrv.x = x[(size_t)b0 * NV + tid];
    llrv.y = x[(size_t)(b0 + 1) * NV + tid];
    s_llr[tid] = llrv;

    int jp[3], voe[3];
#pragma unroll
    for (int k = 0; k < 3; k++) {
        jp[k]  = g_jp[ebase + k];
        voe[k] = g_var_of[ebase + k];
    }
    const int ea = g_eov[tid * 3 + 0], eb = g_eov[tid * 3 + 1], ec = g_eov[tid * 3 + 2];

    __syncthreads();

    float2 llr_e[3];
#pragma unroll
    for (int k = 0; k < 3; k++) llr_e[k] = s_llr[voe[k]];

    float2 tv[3];

    // ---- iteration 1: CN update directly from channel LLRs ----
    cn_half(mask, llr_e, tv);
    s_t[0][ebase + 0] = tv[0];
    s_t[0][ebase + 1] = tv[1];
    s_t[0][ebase + 2] = tv[2];
    __syncthreads();

    // out1 (offset 4*TOT)
    {
        float2 ta = s_t[0][ea], tb = s_t[0][eb], tc = s_t[0][ec];
        size_t off = 4 * TOT + (size_t)b0 * NV;
        out[off + tid]      = sigmoidf(ta.x + tb.x + tc.x + llrv.x);
        out[off + NV + tid] = sigmoidf(ta.y + tb.y + tc.y + llrv.y);
    }

    // ---- iterations 2..5: VN update then fused CN ----
    int src = 0;
#pragma unroll
    for (int li = 0; li < 4; li++) {
        const int dst = src ^ 1;
        float2 vin[3];
#pragma unroll
        for (int k = 0; k < 3; k++) {
            int j1 = jp[k] & 0xFFFF;
            int j2 = jp[k] >> 16;
            float2 t1 = s_t[src][j1];        // one LDS.64 serves both rows
            float2 t2 = s_t[src][j2];
            float2 w  = g_w[li][ebase + k];
            vin[k].x = fmaf(w.x, t1.x, fmaf(w.y, t2.x, llr_e[k].x));
            vin[k].y = fmaf(w.x, t1.y, fmaf(w.y, t2.y, llr_e[k].y));
        }
        cn_half(mask, vin, tv);
        // dst buffer was last read before the previous barrier -> safe
        s_t[dst][ebase + 0] = tv[0];
        s_t[dst][ebase + 1] = tv[1];
        s_t[dst][ebase + 2] = tv[2];
        __syncthreads();

        float2 ta = s_t[dst][ea], tb = s_t[dst][eb], tc = s_t[dst][ec];
        if (li < 3) {
            size_t off = (size_t)(3 - li) * TOT + (size_t)b0 * NV;
            out[off + tid]      = sigmoidf(ta.x + tb.x + tc.x + llrv.x);
            out[off + NV + tid] = sigmoidf(ta.y + tb.y + tc.y + llrv.y);
        } else {
            float w90 = g_w9[tid][0], w91 = g_w9[tid][1], w92 = g_w9[tid][2];
            size_t off = (size_t)b0 * NV;
            out[off + tid]      = sigmoidf(w90 * ta.x + w91 * tb.x + w92 * tc.x + llrv.x);
            out[off + NV + tid] = sigmoidf(w90 * ta.y + w91 * tb.y + w92 * tc.y + llrv.y);
        }
        src = dst;
    }
}

// ---------------- launch ----------------
extern "C" void kernel_launch(void* const* d_in, const int* in_sizes, int n_in,
                              void* d_out, int out_size) {
    // metadata order: x, M_first, M_cn, M_out, bias_matrix, W1, W3, W5, W7, W9, B0..B4
    const float* x     = (const float*)d_in[0];
    const float* M_out = (const float*)d_in[3];
    const float* W1    = (const float*)d_in[5];
    const float* W3    = (const float*)d_in[6];
    const float* W5    = (const float*)d_in[7];
    const float* W7    = (const float*)d_in[8];
    const float* W9    = (const float*)d_in[9];

    prep1<<<(SCAN4 + 255) / 256, 256>>>((const float4*)M_out);
    prep2<<<(4 * NE + 255) / 256, 256>>>(W1, W3, W5, W7, W9);
    bp_main<<<BATCH / ROWS, THREADS>>>(x, (float*)d_out);
}